// round 3
// baseline (speedup 1.0000x reference)
#include <cuda_runtime.h>

#define N_NODES 20000
#define N_EDGES 60000
#define NODE_IN 8
#define HID     64
#define BATCH   256
#define MLP_H   128
#define N_ACT   20000

// ---------------- device scratch (no runtime allocation allowed) ----------------
__device__ float d_h1e[N_EDGES * HID];   // relu(edge_attr @ e1_W1 + e1_b1)
__device__ float d_h2e[N_EDGES * HID];   // relu(edge_attr @ e2_W1 + e2_b1)
__device__ float d_deg[N_NODES];
__device__ float d_agg1[N_NODES * HID];
__device__ float d_h1[N_NODES * HID];
__device__ float d_agg2[N_NODES * HID];
__device__ float d_colsum[HID];
__device__ float d_g[HID];
__device__ float d_y1[BATCH * MLP_H];
__device__ float d_z1[BATCH * MLP_H];
__device__ float d_z2[BATCH * MLP_H];

// ---------------- zero scratch that is atomically accumulated ----------------
__global__ void zero_kernel() {
    int i  = blockIdx.x * blockDim.x + threadIdx.x;
    int gs = gridDim.x * blockDim.x;
    for (int j = i; j < N_NODES * HID; j += gs) { d_agg1[j] = 0.f; d_agg2[j] = 0.f; }
    for (int j = i; j < N_NODES; j += gs) d_deg[j] = 0.f;
    for (int j = i; j < BATCH * MLP_H; j += gs) d_y1[j] = 0.f;
    if (i < HID) d_colsum[i] = 0.f;
}

// ---------------- edge feature MLP stage A for both layers + degree count ----------------
// h1e = relu(ea @ e1_W1 + e1_b1),  h2e = relu(ea @ e2_W1 + e2_b1)
__global__ void edge_feat_kernel(const float* __restrict__ edge_attr,
                                 const int*   __restrict__ edge_index,
                                 const float* __restrict__ W1a, const float* __restrict__ b1a,
                                 const float* __restrict__ W1b, const float* __restrict__ b1b) {
    __shared__ float wa[256], wb[256], ba[64], bb[64], ea[4][4];
    int tid = threadIdx.x;
    wa[tid] = W1a[tid];
    wb[tid] = W1b[tid];
    if (tid < 64) { ba[tid] = b1a[tid]; bb[tid] = b1b[tid]; }
    int e0 = blockIdx.x * 4;
    if (tid < 16) {
        int le = tid >> 2, j = tid & 3;
        int e = e0 + le;
        ea[le][j] = (e < N_EDGES) ? edge_attr[e * 4 + j] : 0.f;
    }
    __syncthreads();
    int c = tid & 63, le = tid >> 6, e = e0 + le;
    if (e < N_EDGES) {
        float s1 = ba[c], s2 = bb[c];
#pragma unroll
        for (int j = 0; j < 4; j++) {
            s1 += ea[le][j] * wa[j * 64 + c];
            s2 += ea[le][j] * wb[j * 64 + c];
        }
        d_h1e[e * 64 + c] = fmaxf(s1, 0.f);
        d_h2e[e * 64 + c] = fmaxf(s2, 0.f);
        if (c == 0) atomicAdd(&d_deg[edge_index[N_EDGES + e]], 1.f);
    }
}

// ---------------- fused per-edge bilinear message + atomic scatter ----------------
// msg[e,o] = sum_i xin[src[e],i] * ( sum_k hE[e,k]*W2[k, i*64+o] + b2[i*64+o] )
// Computed without materializing the [E, IDIM, 64] per-edge weight matrices.
#define TE 128
template<int IDIM>
__launch_bounds__(256, 2)
__global__ void edge_msg_kernel(const float* __restrict__ xin_param,
                                const float* __restrict__ W2,
                                const float* __restrict__ b2,
                                const int*   __restrict__ edge_index,
                                int E) {
    const int* src = edge_index;
    const int* dst = edge_index + E;
    const float* xin = (IDIM == 8) ? xin_param : d_h1;
    const float* hE  = (IDIM == 8) ? d_h1e : d_h2e;
    float*       agg = (IDIM == 8) ? d_agg1 : d_agg2;

    constexpr int HP   = TE + 8;      // 136 (x16B aligned rows)
    constexpr int XP   = IDIM + 1;
    constexpr int WP   = 68;
    constexpr int WROW = IDIM * 64;

    extern __shared__ float sm[];
    float* hT   = sm;                  // [64][HP]  transposed h tile: hT[k][e]
    float* xi   = hT + 64 * HP;        // [TE][XP]  gathered node features
    float* Ws   = xi + TE * XP;        // [64][WP]  one W2 column-slice
    float* bs   = Ws + 64 * WP;        // [64]
    int*   sdst = (int*)(bs + 64);     // [TE]

    int tid   = threadIdx.x;
    int eBase = blockIdx.x * TE;

    for (int idx = tid; idx < TE * 64; idx += 256) {
        int e = idx >> 6, k = idx & 63;
        int ge = eBase + e;
        hT[k * HP + e] = (ge < E) ? hE[ge * 64 + k] : 0.f;
    }
    for (int idx = tid; idx < TE * IDIM; idx += 256) {
        int e = idx / IDIM, i = idx % IDIM;
        int ge = eBase + e;
        xi[e * XP + i] = (ge < E) ? xin[src[ge] * IDIM + i] : 0.f;
    }
    if (tid < TE) {
        int ge = eBase + tid;
        sdst[tid] = (ge < E) ? dst[ge] : 0;
    }
    __syncthreads();

    int to = tid & 15;  int o0 = to * 4;
    int te = tid >> 4;  int e0 = te * 8;

    float acc[8][4];
#pragma unroll
    for (int a = 0; a < 8; a++)
#pragma unroll
        for (int b = 0; b < 4; b++) acc[a][b] = 0.f;

    for (int i = 0; i < IDIM; i++) {
        __syncthreads();  // protect Ws/bs from previous iteration's readers
        for (int idx = tid; idx < 64 * 64; idx += 256) {
            int k = idx >> 6, o = idx & 63;
            Ws[k * WP + o] = W2[k * WROW + i * 64 + o];
        }
        if (tid < 64) bs[tid] = b2[i * 64 + tid];
        __syncthreads();

        float hv[8];
#pragma unroll
        for (int a = 0; a < 8; a++) hv[a] = xi[(e0 + a) * XP + i];

        float4 bv = *(const float4*)&bs[o0];
#pragma unroll
        for (int a = 0; a < 8; a++) {
            acc[a][0] += hv[a] * bv.x; acc[a][1] += hv[a] * bv.y;
            acc[a][2] += hv[a] * bv.z; acc[a][3] += hv[a] * bv.w;
        }

        const float* wsp = Ws + o0;
        const float* htp = hT + e0;
#define EMROW(ai, hval) { float p = hv[ai] * (hval); \
        acc[ai][0] += p * w.x; acc[ai][1] += p * w.y; \
        acc[ai][2] += p * w.z; acc[ai][3] += p * w.w; }
#pragma unroll 8
        for (int k = 0; k < 64; k++) {
            float4 w  = *(const float4*)(wsp + k * WP);
            float4 hA = *(const float4*)(htp + k * HP);
            float4 hB = *(const float4*)(htp + k * HP + 4);
            EMROW(0, hA.x) EMROW(1, hA.y) EMROW(2, hA.z) EMROW(3, hA.w)
            EMROW(4, hB.x) EMROW(5, hB.y) EMROW(6, hB.z) EMROW(7, hB.w)
        }
#undef EMROW
    }

#pragma unroll
    for (int a = 0; a < 8; a++) {
        int ge = eBase + e0 + a;
        if (ge < E) {
            float* p = agg + sdst[e0 + a] * 64 + o0;
            atomicAdd(p + 0, acc[a][0]);
            atomicAdd(p + 1, acc[a][1]);
            atomicAdd(p + 2, acc[a][2]);
            atomicAdd(p + 3, acc[a][3]);
        }
    }
}

// ---------------- node update 1: h1 = relu(agg1/deg + x@root1 + bias1) ----------------
__global__ void node_update1(const float* __restrict__ x,
                             const float* __restrict__ root1,
                             const float* __restrict__ bias1) {
    __shared__ float r1[512], b1s[64], xs[4][8], dn[4];
    int tid = threadIdx.x;
    r1[tid] = root1[tid];
    r1[tid + 256] = root1[tid + 256];
    if (tid < 64) b1s[tid] = bias1[tid];
    int n0 = blockIdx.x * 4;
    if (tid < 32) {
        int ln = tid >> 3, j = tid & 7;
        int n = n0 + ln;
        xs[ln][j] = (n < N_NODES) ? x[n * 8 + j] : 0.f;
    }
    if (tid < 4) {
        int n = n0 + tid;
        dn[tid] = (n < N_NODES) ? fmaxf(d_deg[n], 1.f) : 1.f;
    }
    __syncthreads();
    int c = tid & 63, ln = tid >> 6, n = n0 + ln;
    if (n < N_NODES) {
        float s = d_agg1[n * 64 + c] / dn[ln] + b1s[c];
#pragma unroll
        for (int j = 0; j < 8; j++) s += xs[ln][j] * r1[j * 64 + c];
        d_h1[n * 64 + c] = fmaxf(s, 0.f);
    }
}

// ---------------- node update 2 + column-sum for mean pool (h2 never stored) ----------------
__global__ void node_update2(const float* __restrict__ root2,
                             const float* __restrict__ bias2) {
    __shared__ float h1s[64 * 65];
    __shared__ float r2s[64 * 64];
    __shared__ float b2s[64];
    __shared__ float dn[64];
    __shared__ float colpart[4 * 64];
    int tid = threadIdx.x;
    int n0 = blockIdx.x * 64;
    for (int idx = tid; idx < 64 * 64; idx += 256) r2s[idx] = root2[idx];
    for (int idx = tid; idx < 64 * 64; idx += 256) {
        int ln = idx >> 6, k = idx & 63;
        int n = n0 + ln;
        h1s[ln * 65 + k] = (n < N_NODES) ? d_h1[n * 64 + k] : 0.f;
    }
    if (tid < 64) {
        b2s[tid] = bias2[tid];
        int n = n0 + tid;
        dn[tid] = (n < N_NODES) ? fmaxf(d_deg[n], 1.f) : 1.f;
    }
    __syncthreads();
    int c = tid & 63, ng = tid >> 6;
    float csum = 0.f;
    for (int j = 0; j < 16; j++) {
        int ln = ng + 4 * j;
        int n = n0 + ln;
        if (n < N_NODES) {
            float s = d_agg2[n * 64 + c] / dn[ln] + b2s[c];
#pragma unroll 8
            for (int k = 0; k < 64; k++) s += h1s[ln * 65 + k] * r2s[k * 64 + c];
            csum += fmaxf(s, 0.f);
        }
    }
    colpart[ng * 64 + c] = csum;
    __syncthreads();
    if (tid < 64) {
        float t = colpart[tid] + colpart[64 + tid] + colpart[128 + tid] + colpart[192 + tid];
        atomicAdd(&d_colsum[tid], t);
    }
}

// ---------------- g = mean(h2) @ projW + projb ----------------
__global__ void g_kernel(const float* __restrict__ projW, const float* __restrict__ projb) {
    __shared__ float cs[64];
    int tid = threadIdx.x;
    cs[tid] = d_colsum[tid] * (1.f / (float)N_NODES);
    __syncthreads();
    float s = projb[tid];
    for (int c = 0; c < 64; c++) s += cs[c] * projW[c * 64 + tid];
    d_g[tid] = s;
}

// ---------------- MLP layer 1, split-K over the 20000-long reduction ----------------
__global__ void mlp1_main(const float* __restrict__ a, const float* __restrict__ mW1) {
    __shared__ __align__(16) float aT[64 * 36];
    __shared__ __align__(16) float Wt[64 * 132];
    int tid = threadIdx.x;
    int m0 = blockIdx.x * 32;
    int ks = blockIdx.y * 313;
    int ke = min(N_ACT, ks + 313);
    int tj = tid & 31, tb = tid >> 5;
    int j0 = tj * 4, b0 = tb * 4;
    float acc[4][4];
#pragma unroll
    for (int p = 0; p < 4; p++)
#pragma unroll
        for (int q = 0; q < 4; q++) acc[p][q] = 0.f;

    for (int kk = ks; kk < ke; kk += 64) {
        int klen = ke - kk;
        __syncthreads();
        for (int idx = tid; idx < 2048; idx += 256) {
            int b = idx >> 6, k = idx & 63;
            aT[k * 36 + b] = (k < klen) ? a[(m0 + b) * N_ACT + kk + k] : 0.f;
        }
        for (int idx = tid; idx < 8192; idx += 256) {
            int k = idx >> 7, j = idx & 127;
            Wt[k * 132 + j] = (k < klen) ? mW1[(kk + k) * 128 + j] : 0.f;
        }
        __syncthreads();
#pragma unroll 8
        for (int k = 0; k < 64; k++) {
            float4 av = *(const float4*)&aT[k * 36 + b0];
            float4 wv = *(const float4*)&Wt[k * 132 + j0];
            acc[0][0] += av.x * wv.x; acc[0][1] += av.x * wv.y; acc[0][2] += av.x * wv.z; acc[0][3] += av.x * wv.w;
            acc[1][0] += av.y * wv.x; acc[1][1] += av.y * wv.y; acc[1][2] += av.y * wv.z; acc[1][3] += av.y * wv.w;
            acc[2][0] += av.z * wv.x; acc[2][1] += av.z * wv.y; acc[2][2] += av.z * wv.z; acc[2][3] += av.z * wv.w;
            acc[3][0] += av.w * wv.x; acc[3][1] += av.w * wv.y; acc[3][2] += av.w * wv.z; acc[3][3] += av.w * wv.w;
        }
    }
#pragma unroll
    for (int p = 0; p < 4; p++)
#pragma unroll
        for (int q = 0; q < 4; q++)
            atomicAdd(&d_y1[(m0 + b0 + p) * 128 + j0 + q], acc[p][q]);
}

// ---------------- MLP layer 1 finish: add g-part + bias, relu ----------------
__global__ void mlp1_finish(const float* __restrict__ mW1, const float* __restrict__ mb1) {
    __shared__ float gs[64];
    int tid = threadIdx.x;
    if (tid < 64) gs[tid] = d_g[tid];
    __syncthreads();
    int idx = blockIdx.x * 256 + tid;
    int j = idx & 127;
    float s = d_y1[idx] + mb1[j];
    for (int c = 0; c < 64; c++) s += gs[c] * mW1[(N_ACT + c) * 128 + j];
    d_z1[idx] = fmaxf(s, 0.f);
}

// ---------------- MLP layer 2 ----------------
__global__ void mlp2_kernel(const float* __restrict__ mW2, const float* __restrict__ mb2) {
    __shared__ float zs[2][128];
    int tid = threadIdx.x;
    int b0 = blockIdx.x * 2;
    zs[tid >> 7][tid & 127] = d_z1[b0 * 128 + tid];
    __syncthreads();
    int lb = tid >> 7, j = tid & 127;
    float s = mb2[j];
#pragma unroll 4
    for (int k = 0; k < 128; k++) s += zs[lb][k] * mW2[k * 128 + j];
    d_z2[(b0 + lb) * 128 + j] = fmaxf(s, 0.f);
}

// ---------------- MLP layer 3 ----------------
__global__ void mlp3_kernel(const float* __restrict__ mW3, const float* __restrict__ mb3,
                            float* __restrict__ out) {
    __shared__ float w3[128];
    int tid = threadIdx.x;
    if (tid < 128) w3[tid] = mW3[tid];
    __syncthreads();
    float s = mb3[0];
    for (int j = 0; j < 128; j++) s += d_z2[tid * 128 + j] * w3[j];
    out[tid] = s;
}

// ---------------- launcher ----------------
extern "C" void kernel_launch(void* const* d_in, const int* in_sizes, int n_in,
                              void* d_out, int out_size) {
    const float* x     = (const float*)d_in[0];
    const int*   ei    = (const int*)  d_in[1];
    const float* ea    = (const float*)d_in[2];
    const float* a     = (const float*)d_in[3];
    const float* e1W1  = (const float*)d_in[4];
    const float* e1b1  = (const float*)d_in[5];
    const float* e1W2  = (const float*)d_in[6];
    const float* e1b2  = (const float*)d_in[7];
    const float* root1 = (const float*)d_in[8];
    const float* bias1 = (const float*)d_in[9];
    const float* e2W1  = (const float*)d_in[10];
    const float* e2b1  = (const float*)d_in[11];
    const float* e2W2  = (const float*)d_in[12];
    const float* e2b2  = (const float*)d_in[13];
    const float* root2 = (const float*)d_in[14];
    const float* bias2 = (const float*)d_in[15];
    const float* projW = (const float*)d_in[16];
    const float* projb = (const float*)d_in[17];
    const float* mW1   = (const float*)d_in[18];
    const float* mb1   = (const float*)d_in[19];
    const float* mW2   = (const float*)d_in[20];
    const float* mb2   = (const float*)d_in[21];
    const float* mW3   = (const float*)d_in[22];
    const float* mb3   = (const float*)d_in[23];
    float* out = (float*)d_out;

    // dynamic shared sizes for the fused edge-message kernels
    const int s8  = (64 * 136 + 128 * 9  + 64 * 68 + 64 + 128) * 4;  // 57600 B
    const int s64 = (64 * 136 + 128 * 65 + 64 * 68 + 64 + 128) * 4;  // 86272 B
    cudaFuncSetAttribute(edge_msg_kernel<8>,  cudaFuncAttributeMaxDynamicSharedMemorySize, s8);
    cudaFuncSetAttribute(edge_msg_kernel<64>, cudaFuncAttributeMaxDynamicSharedMemorySize, s64);

    zero_kernel<<<512, 256>>>();
    edge_feat_kernel<<<(N_EDGES + 3) / 4, 256>>>(ea, ei, e1W1, e1b1, e2W1, e2b1);
    edge_msg_kernel<8><<<(N_EDGES + TE - 1) / TE, 256, s8>>>(x, e1W2, e1b2, ei, N_EDGES);
    node_update1<<<(N_NODES + 3) / 4, 256>>>(x, root1, bias1);
    edge_msg_kernel<64><<<(N_EDGES + TE - 1) / TE, 256, s64>>>(x, e2W2, e2b2, ei, N_EDGES);
    node_update2<<<(N_NODES + 63) / 64, 256>>>(root2, bias2);
    g_kernel<<<1, 64>>>(projW, projb);
    mlp1_main<<<dim3(8, 64), 256>>>(a, mW1);
    mlp1_finish<<<128, 256>>>(mW1, mb1);
    mlp2_kernel<<<128, 256>>>(mW2, mb2);
    mlp3_kernel<<<1, 256>>>(mW3, mb3, out);
}